// round 7
// baseline (speedup 1.0000x reference)
#include <cuda_runtime.h>
#include <cstdint>

// DynamicGRU: B=32, T=2048, D=256, N=256
// Phase 1: PRE[row,0:512]   = x @ W_g[0:256,:] + b_g
//          PRE[row,512:768] = x @ W_c[0:256,:] + b_c     (parallel GEMM)
// Phase 2: persistent scan, one 4-CTA cluster per batch row; recurrent
//          weight slices resident in smem; h / r*h replicated via DSMEM.

#define BATCH_ 32
#define T_     2048

// 201 MB scratch (static __device__ allocation is allowed).
__device__ float g_pre[(size_t)BATCH_ * T_ * 768];

// ---------------------------------------------------------------------------
// Phase 1: fp32 tiled GEMM  [65536,256] x [256,768] -> g_pre (bias folded).
// BM=128, BN=64, BK=16, 256 threads, 8x4 register tile.
// ---------------------------------------------------------------------------
__global__ __launch_bounds__(256) void gemm_pre_kernel(
    const float* __restrict__ x,
    const float* __restrict__ Wg, const float* __restrict__ bg,
    const float* __restrict__ Wc, const float* __restrict__ bc)
{
    __shared__ float As[16 * 132];  // [k][m], padded row stride 132
    __shared__ float Bs[16 * 64];   // [k][n]

    const int bn  = blockIdx.x;   // 0..11  (64-wide output column block)
    const int bm  = blockIdx.y;   // 0..511 (128-row block)
    const int tid = threadIdx.x;

    const float* Wp; int ldw, coff; const float* bias;
    if (bn < 8) { Wp = Wg; ldw = 512; coff = bn * 64;        bias = bg + coff; }
    else        { Wp = Wc; ldw = 256; coff = (bn - 8) * 64;  bias = bc + coff; }

    const int tx   = tid & 15;          // output col group (4 cols)
    const int ty   = tid >> 4;          // output row group (8 rows)
    const int arow = tid >> 2;          // 0..63
    const int acol = (tid & 3) * 4;     // 0,4,8,12
    const int brow = tid >> 4;          // 0..15
    const int bcol = (tid & 15) * 4;    // 0..60

    const float* Ag = x + (size_t)(bm * 128) * 256;

    float acc[8][4];
#pragma unroll
    for (int i = 0; i < 8; ++i)
#pragma unroll
        for (int j = 0; j < 4; ++j) acc[i][j] = 0.f;

    for (int kt = 0; kt < 256; kt += 16) {
        float4 a0 = *(const float4*)(Ag + (size_t)arow * 256 + kt + acol);
        float4 a1 = *(const float4*)(Ag + (size_t)(arow + 64) * 256 + kt + acol);
        float4 b0 = *(const float4*)(Wp + (size_t)(kt + brow) * ldw + coff + bcol);

        As[(acol + 0) * 132 + arow]      = a0.x;
        As[(acol + 1) * 132 + arow]      = a0.y;
        As[(acol + 2) * 132 + arow]      = a0.z;
        As[(acol + 3) * 132 + arow]      = a0.w;
        As[(acol + 0) * 132 + arow + 64] = a1.x;
        As[(acol + 1) * 132 + arow + 64] = a1.y;
        As[(acol + 2) * 132 + arow + 64] = a1.z;
        As[(acol + 3) * 132 + arow + 64] = a1.w;
        *(float4*)&Bs[brow * 64 + bcol] = b0;
        __syncthreads();

#pragma unroll
        for (int k = 0; k < 16; ++k) {
            float4 av0 = *(const float4*)&As[k * 132 + ty * 8];
            float4 av1 = *(const float4*)&As[k * 132 + ty * 8 + 4];
            float4 bv  = *(const float4*)&Bs[k * 64 + tx * 4];
            float am[8] = {av0.x, av0.y, av0.z, av0.w,
                           av1.x, av1.y, av1.z, av1.w};
#pragma unroll
            for (int i = 0; i < 8; ++i) {
                acc[i][0] += am[i] * bv.x;
                acc[i][1] += am[i] * bv.y;
                acc[i][2] += am[i] * bv.z;
                acc[i][3] += am[i] * bv.w;
            }
        }
        __syncthreads();
    }

    float4 bb = *(const float4*)(bias + tx * 4);
    float* Og = g_pre + (size_t)(bm * 128) * 768 + bn * 64;
#pragma unroll
    for (int i = 0; i < 8; ++i) {
        float4 o;
        o.x = acc[i][0] + bb.x;
        o.y = acc[i][1] + bb.y;
        o.z = acc[i][2] + bb.z;
        o.w = acc[i][3] + bb.w;
        *(float4*)(Og + (size_t)(ty * 8 + i) * 768 + tx * 4) = o;
    }
}

// ---------------------------------------------------------------------------
// Phase 2 helpers
// ---------------------------------------------------------------------------
__device__ __forceinline__ void cluster_sync_() {
    asm volatile("barrier.cluster.arrive.aligned;" ::: "memory");
    asm volatile("barrier.cluster.wait.aligned;" ::: "memory");
}
__device__ __forceinline__ uint32_t smem_u32_(const void* p) {
    uint32_t a;
    asm("{ .reg .u64 t; cvta.to.shared.u64 t, %1; cvt.u32.u64 %0, t; }"
        : "=r"(a) : "l"(p));
    return a;
}
__device__ __forceinline__ void st_cluster_f32_(uint32_t laddr, int rank, float v) {
    uint32_t ra;
    asm volatile("mapa.shared::cluster.u32 %0, %1, %2;" : "=r"(ra) : "r"(laddr), "r"(rank));
    asm volatile("st.shared::cluster.f32 [%0], %1;" :: "r"(ra), "f"(v) : "memory");
}

// Dynamic smem layout (floats):
//   wgate [256][128]  (local r cols 0..63, local u cols 64..127)   32768
//   wcc   [256][64]                                                16384
//   hbuf[256] rhbuf[256] ubuf[64] pbuf[2][192] redA[2048] redB[1024]
#define SM_WGATE 0
#define SM_WCC   32768
#define SM_HBUF  49152
#define SM_RHBUF 49408
#define SM_UBUF  49664
#define SM_PBUF  49728
#define SM_REDA  50112
#define SM_REDB  52160
#define SM_FLOATS 53184
#define SMEM_BYTES (SM_FLOATS * 4)

__global__ void __cluster_dims__(4, 1, 1) __launch_bounds__(512, 1)
gru_rec_kernel(const float* __restrict__ Wg, const float* __restrict__ Wc,
               const float* __restrict__ h0, float* __restrict__ out)
{
    extern __shared__ float sm[];
    float* wgate = sm + SM_WGATE;
    float* wcc   = sm + SM_WCC;
    float* hbuf  = sm + SM_HBUF;
    float* rhbuf = sm + SM_RHBUF;
    float* ubuf  = sm + SM_UBUF;
    float* pbuf  = sm + SM_PBUF;   // [2][192]
    float* redA  = sm + SM_REDA;   // [16][128]
    float* redB  = sm + SM_REDB;   // [16][64]

    const int tid = threadIdx.x;
    uint32_t rank;
    asm("mov.u32 %0, %%cluster_ctarank;" : "=r"(rank));
    const int b = blockIdx.x >> 2;

    // Load recurrent weight slices (resident for all 2048 steps).
    for (int i = tid; i < 32768; i += 512) {
        int k = i >> 7, c = i & 127;
        wgate[i] = (c < 64)
            ? Wg[(size_t)(256 + k) * 512 + rank * 64 + c]
            : Wg[(size_t)(256 + k) * 512 + 256 + rank * 64 + (c - 64)];
    }
    for (int i = tid; i < 16384; i += 512) {
        int k = i >> 6, c = i & 63;
        wcc[i] = Wc[(size_t)(256 + k) * 256 + rank * 64 + c];
    }
    for (int i = tid; i < 256; i += 512) hbuf[i] = h0[b * 256 + i];

    // Pre-activation index this thread prefetches (tid < 192).
    int preidx = 0;
    if      (tid < 64)  preidx = rank * 64 + tid;                 // r
    else if (tid < 128) preidx = 256 + rank * 64 + (tid - 64);    // u
    else if (tid < 192) preidx = 512 + rank * 64 + (tid - 128);   // c

    const float* prow = g_pre + (size_t)b * T_ * 768;
    float*       orow = out   + (size_t)b * T_ * 256;

    if (tid < 192) pbuf[tid] = prow[preidx];   // step 0 pre-activations
    __syncthreads();
    cluster_sync_();

    const uint32_t rh_u32 = smem_u32_(rhbuf);
    const uint32_t h_u32  = smem_u32_(hbuf);

    const int cg = tid & 31;   // gate: 4-col group (128 cols)
    const int ks = tid >> 5;   // k-slice: 16 k each (warp-uniform)

    for (int t = 0; t < T_; ++t) {
        const int cur = t & 1, nxt = cur ^ 1;

        // Prefetch next step's pre-activations (consumed at step bottom).
        float pre_next = 0.f;
        if (tid < 192 && t + 1 < T_)
            pre_next = prow[(size_t)(t + 1) * 768 + preidx];

        // ---- Gates: [128 local cols] = sigmoid(h . Wgate + pre) ----
        float hv[16];
#pragma unroll
        for (int j = 0; j < 16; j += 4) {
            float4 h4 = *(const float4*)&hbuf[ks * 16 + j];
            hv[j] = h4.x; hv[j + 1] = h4.y; hv[j + 2] = h4.z; hv[j + 3] = h4.w;
        }
        {
            float a0 = 0.f, a1 = 0.f, a2 = 0.f, a3 = 0.f;
            const float* wp = wgate + (size_t)ks * 16 * 128 + cg * 4;
#pragma unroll
            for (int j = 0; j < 16; ++j) {
                float4 w = *(const float4*)&wp[j * 128];
                a0 += hv[j] * w.x; a1 += hv[j] * w.y;
                a2 += hv[j] * w.z; a3 += hv[j] * w.w;
            }
            *(float4*)&redA[ks * 128 + cg * 4] = make_float4(a0, a1, a2, a3);
        }
        __syncthreads();

        if (tid < 128) {
            float s = pbuf[cur * 192 + tid];
#pragma unroll
            for (int q = 0; q < 16; ++q) s += redA[q * 128 + tid];
            float g = 1.f / (1.f + __expf(-s));
            if (tid < 64) {
                float rh = g * hbuf[rank * 64 + tid];
                uint32_t a = rh_u32 + (rank * 64 + tid) * 4;
#pragma unroll
                for (int rk = 0; rk < 4; ++rk) st_cluster_f32_(a, rk, rh);
            } else {
                ubuf[tid - 64] = g;
            }
        }
        cluster_sync_();   // rhbuf complete cluster-wide

        // ---- Candidate: [64 local cols] = tanh(rh . Wcc + pre_c) ----
        float rv[16];
#pragma unroll
        for (int j = 0; j < 16; j += 4) {
            float4 r4 = *(const float4*)&rhbuf[ks * 16 + j];
            rv[j] = r4.x; rv[j + 1] = r4.y; rv[j + 2] = r4.z; rv[j + 3] = r4.w;
        }
        {
            float c0 = 0.f, c1 = 0.f;
            const float* wp = wcc + (size_t)ks * 16 * 64 + cg * 2;
#pragma unroll
            for (int j = 0; j < 16; ++j) {
                float2 w = *(const float2*)&wp[j * 64];
                c0 += rv[j] * w.x; c1 += rv[j] * w.y;
            }
            *(float2*)&redB[ks * 64 + cg * 2] = make_float2(c0, c1);
        }
        __syncthreads();

        if (tid < 64) {
            float s = pbuf[cur * 192 + 128 + tid];
#pragma unroll
            for (int q = 0; q < 16; ++q) s += redB[q * 64 + tid];
            float c  = tanhf(s);
            float u  = ubuf[tid];
            float hn = u * hbuf[rank * 64 + tid] + (1.f - u) * c;
            orow[(size_t)t * 256 + rank * 64 + tid] = hn;
            uint32_t a = h_u32 + (rank * 64 + tid) * 4;
#pragma unroll
            for (int rk = 0; rk < 4; ++rk) st_cluster_f32_(a, rk, hn);
        }
        if (tid < 192) pbuf[nxt * 192 + tid] = pre_next;
        cluster_sync_();   // hbuf complete cluster-wide; pbuf ready
    }
}

// ---------------------------------------------------------------------------
extern "C" void kernel_launch(void* const* d_in, const int* in_sizes, int n_in,
                              void* d_out, int out_size) {
    const float* x  = (const float*)d_in[0];
    const float* h0 = (const float*)d_in[1];
    const float* Wg = (const float*)d_in[2];
    const float* bg = (const float*)d_in[3];
    const float* Wc = (const float*)d_in[4];
    const float* bc = (const float*)d_in[5];
    float* out = (float*)d_out;

    cudaFuncSetAttribute(gru_rec_kernel,
                         cudaFuncAttributeMaxDynamicSharedMemorySize, SMEM_BYTES);

    dim3 g1(12, 512);
    gemm_pre_kernel<<<g1, 256>>>(x, Wg, bg, Wc, bc);
    gru_rec_kernel<<<128, 512, SMEM_BYTES>>>(Wg, Wc, h0, out);
}

// round 8
// speedup vs baseline: 1.2351x; 1.2351x over previous
#include <cuda_runtime.h>
#include <cstdint>

// DynamicGRU: B=32, T=2048, D=256, N=256
// Phase 1: PRE = x @ [W_g[:256,:] | W_c[:256,:]] + bias  (parallel GEMM)
// Phase 2: persistent scan, one 4-CTA cluster per batch row.
//          Recurrent weights REGISTER-resident (96 floats/thread),
//          h / r*h replicated cluster-wide via st.shared::cluster,
//          MACs via packed fma.rn.f32x2 (FFMA2).

#define BATCH_ 32
#define T_     2048

// 201 MB scratch (static __device__ allocation is allowed).
__device__ float g_pre[(size_t)BATCH_ * T_ * 768];

// ---------------------------------------------------------------------------
// Phase 1: fp32 tiled GEMM  [65536,256] x [256,768] -> g_pre (bias folded).
// ---------------------------------------------------------------------------
__global__ __launch_bounds__(256) void gemm_pre_kernel(
    const float* __restrict__ x,
    const float* __restrict__ Wg, const float* __restrict__ bg,
    const float* __restrict__ Wc, const float* __restrict__ bc)
{
    __shared__ float As[16 * 132];
    __shared__ float Bs[16 * 64];

    const int bn  = blockIdx.x;
    const int bm  = blockIdx.y;
    const int tid = threadIdx.x;

    const float* Wp; int ldw, coff; const float* bias;
    if (bn < 8) { Wp = Wg; ldw = 512; coff = bn * 64;        bias = bg + coff; }
    else        { Wp = Wc; ldw = 256; coff = (bn - 8) * 64;  bias = bc + coff; }

    const int tx   = tid & 15;
    const int ty   = tid >> 4;
    const int arow = tid >> 2;
    const int acol = (tid & 3) * 4;
    const int brow = tid >> 4;
    const int bcol = (tid & 15) * 4;

    const float* Ag = x + (size_t)(bm * 128) * 256;

    float acc[8][4];
#pragma unroll
    for (int i = 0; i < 8; ++i)
#pragma unroll
        for (int j = 0; j < 4; ++j) acc[i][j] = 0.f;

    for (int kt = 0; kt < 256; kt += 16) {
        float4 a0 = *(const float4*)(Ag + (size_t)arow * 256 + kt + acol);
        float4 a1 = *(const float4*)(Ag + (size_t)(arow + 64) * 256 + kt + acol);
        float4 b0 = *(const float4*)(Wp + (size_t)(kt + brow) * ldw + coff + bcol);

        As[(acol + 0) * 132 + arow]      = a0.x;
        As[(acol + 1) * 132 + arow]      = a0.y;
        As[(acol + 2) * 132 + arow]      = a0.z;
        As[(acol + 3) * 132 + arow]      = a0.w;
        As[(acol + 0) * 132 + arow + 64] = a1.x;
        As[(acol + 1) * 132 + arow + 64] = a1.y;
        As[(acol + 2) * 132 + arow + 64] = a1.z;
        As[(acol + 3) * 132 + arow + 64] = a1.w;
        *(float4*)&Bs[brow * 64 + bcol] = b0;
        __syncthreads();

#pragma unroll
        for (int k = 0; k < 16; ++k) {
            float4 av0 = *(const float4*)&As[k * 132 + ty * 8];
            float4 av1 = *(const float4*)&As[k * 132 + ty * 8 + 4];
            float4 bv  = *(const float4*)&Bs[k * 64 + tx * 4];
            float am[8] = {av0.x, av0.y, av0.z, av0.w,
                           av1.x, av1.y, av1.z, av1.w};
#pragma unroll
            for (int i = 0; i < 8; ++i) {
                acc[i][0] += am[i] * bv.x;
                acc[i][1] += am[i] * bv.y;
                acc[i][2] += am[i] * bv.z;
                acc[i][3] += am[i] * bv.w;
            }
        }
        __syncthreads();
    }

    float4 bb = *(const float4*)(bias + tx * 4);
    float* Og = g_pre + (size_t)(bm * 128) * 768 + bn * 64;
#pragma unroll
    for (int i = 0; i < 8; ++i) {
        float4 o;
        o.x = acc[i][0] + bb.x;
        o.y = acc[i][1] + bb.y;
        o.z = acc[i][2] + bb.z;
        o.w = acc[i][3] + bb.w;
        *(float4*)(Og + (size_t)(ty * 8 + i) * 768 + tx * 4) = o;
    }
}

// ---------------------------------------------------------------------------
// Phase 2 helpers
// ---------------------------------------------------------------------------
__device__ __forceinline__ void cluster_sync_() {
    asm volatile("barrier.cluster.arrive.aligned;" ::: "memory");
    asm volatile("barrier.cluster.wait.aligned;" ::: "memory");
}
__device__ __forceinline__ uint32_t smem_u32_(const void* p) {
    uint32_t a;
    asm("{ .reg .u64 t; cvta.to.shared.u64 t, %1; cvt.u32.u64 %0, t; }"
        : "=r"(a) : "l"(p));
    return a;
}
__device__ __forceinline__ void st_cluster_f32_(uint32_t laddr, int rank, float v) {
    uint32_t ra;
    asm volatile("mapa.shared::cluster.u32 %0, %1, %2;" : "=r"(ra) : "r"(laddr), "r"(rank));
    asm volatile("st.shared::cluster.f32 [%0], %1;" :: "r"(ra), "f"(v) : "memory");
}
__device__ __forceinline__ uint64_t pack2_(float a, float b) {
    uint64_t r;
    asm("mov.b64 %0, {%1, %2};" : "=l"(r) : "f"(a), "f"(b));
    return r;
}
__device__ __forceinline__ void unpack2_(uint64_t v, float& a, float& b) {
    asm("mov.b64 {%0, %1}, %2;" : "=f"(a), "=f"(b) : "l"(v));
}
__device__ __forceinline__ void fma2_(uint64_t& d, uint64_t a, uint64_t b) {
    asm("fma.rn.f32x2 %0, %1, %2, %0;" : "+l"(d) : "l"(a), "l"(b));
}
__device__ __forceinline__ void lds_v2u64_(uint32_t addr, uint64_t& a, uint64_t& b) {
    asm volatile("ld.shared.v2.u64 {%0, %1}, [%2];" : "=l"(a), "=l"(b) : "r"(addr));
}

// ---------------------------------------------------------------------------
// Phase 2: grid = 128 CTAs, cluster(4,1,1), 512 threads. CTA rank owns
// h-slice [64r, 64r+64). Warp w: gate slice sg=w&3 (64 k), 32 gate cols
// (w>>2)*32+lane; cand slice sc=w&7 (32 k), 32 cand... cols (w>>3)*32+lane.
// Weights in registers: 32 u64 (gates) + 16 u64 (cand) per thread.
// ---------------------------------------------------------------------------
__global__ void __cluster_dims__(4, 1, 1) __launch_bounds__(512, 1)
gru_rec_kernel(const float* __restrict__ Wg, const float* __restrict__ Wc,
               const float* __restrict__ h0, float* __restrict__ out)
{
    __shared__ __align__(16) float hbuf[256];
    __shared__ __align__(16) float rhbuf[256];
    __shared__ float ubuf[64];
    __shared__ float pbuf[2 * 192];
    __shared__ __align__(16) float redA[128 * 4];   // [col][slice]
    __shared__ __align__(16) float redB[64 * 8];    // [col][slice]

    const int tid  = threadIdx.x;
    const int w    = tid >> 5;
    const int lane = tid & 31;
    uint32_t rank;
    asm("mov.u32 %0, %%cluster_ctarank;" : "=r"(rank));
    const int b = blockIdx.x >> 2;

    // ---- gate mapping: slice sg (k quarter), column col (0..127 local) ----
    const int sg  = w & 3;
    const int col = (w >> 2) * 32 + lane;          // 0..127
    const int gcol = (col < 64) ? (int)(rank * 64 + col)
                                : (int)(256 + rank * 64 + (col - 64));
    // ---- cand mapping: slice sc (k eighth), column cc (0..63 local) ----
    const int sc  = w & 7;
    const int cc  = (w >> 3) * 32 + lane;          // 0..63
    const int ccol = rank * 64 + cc;

    // ---- load weights into registers (one-time) ----
    uint64_t wg2[32];
#pragma unroll
    for (int j = 0; j < 16; ++j) {
        int k = sg * 64 + j * 4;
        float w0 = Wg[(size_t)(256 + k + 0) * 512 + gcol];
        float w1 = Wg[(size_t)(256 + k + 1) * 512 + gcol];
        float w2 = Wg[(size_t)(256 + k + 2) * 512 + gcol];
        float w3 = Wg[(size_t)(256 + k + 3) * 512 + gcol];
        wg2[2 * j]     = pack2_(w0, w1);
        wg2[2 * j + 1] = pack2_(w2, w3);
    }
    uint64_t wc2[16];
#pragma unroll
    for (int j = 0; j < 8; ++j) {
        int k = sc * 32 + j * 4;
        float w0 = Wc[(size_t)(256 + k + 0) * 256 + ccol];
        float w1 = Wc[(size_t)(256 + k + 1) * 256 + ccol];
        float w2 = Wc[(size_t)(256 + k + 2) * 256 + ccol];
        float w3 = Wc[(size_t)(256 + k + 3) * 256 + ccol];
        wc2[2 * j]     = pack2_(w0, w1);
        wc2[2 * j + 1] = pack2_(w2, w3);
    }

    for (int i = tid; i < 256; i += 512) hbuf[i] = h0[b * 256 + i];

    // pre-activation slot this thread prefetches (tid < 192)
    int preidx = 0;
    if      (tid < 64)  preidx = rank * 64 + tid;               // r
    else if (tid < 128) preidx = 256 + rank * 64 + (tid - 64);  // u
    else if (tid < 192) preidx = 512 + rank * 64 + (tid - 128); // c

    const float* prow = g_pre + (size_t)b * T_ * 768;
    float*       orow = out   + (size_t)b * T_ * 256;

    if (tid < 192) pbuf[tid] = prow[preidx];
    __syncthreads();
    cluster_sync_();

    const uint32_t hb    = smem_u32_(hbuf);
    const uint32_t rhb   = smem_u32_(rhbuf);
    const uint32_t ha_g  = hb  + sg * 256;   // gate h base (bytes)
    const uint32_t ra_c  = rhb + sc * 128;   // cand rh base (bytes)

    for (int t = 0; t < T_; ++t) {
        const int cur = (t & 1) * 192, nxt = ((t & 1) ^ 1) * 192;

        // prefetch next step's pre-activations
        float pre_next = 0.f;
        if (tid < 192 && t + 1 < T_)
            pre_next = prow[(size_t)(t + 1) * 768 + preidx];

        // ---- gates partial: h[sg*64 .. +64) . wg ----
        {
            uint64_t a0 = 0, a1 = 0;
#pragma unroll
            for (int j = 0; j < 16; ++j) {
                uint64_t h01, h23;
                lds_v2u64_(ha_g + j * 16, h01, h23);
                fma2_(a0, wg2[2 * j],     h01);
                fma2_(a1, wg2[2 * j + 1], h23);
            }
            float x0, x1, y0, y1;
            unpack2_(a0, x0, x1);
            unpack2_(a1, y0, y1);
            redA[col * 4 + sg] = (x0 + x1) + (y0 + y1);
        }
        __syncthreads();

        // ---- gate finalize: 128 threads, one column each ----
        if (tid < 128) {
            float4 p4 = *(const float4*)&redA[tid * 4];
            float s = p4.x + p4.y + p4.z + p4.w + pbuf[cur + tid];
            float g = 1.f / (1.f + __expf(-s));
            if (tid < 64) {
                float rh = g * hbuf[rank * 64 + tid];
                uint32_t a = rhb + (rank * 64 + tid) * 4;
#pragma unroll
                for (int rk = 0; rk < 4; ++rk) st_cluster_f32_(a, rk, rh);
            } else {
                ubuf[tid - 64] = g;
            }
        }
        cluster_sync_();   // rhbuf complete cluster-wide

        // ---- candidate partial: rh[sc*32 .. +32) . wc ----
        {
            uint64_t c0 = 0, c1 = 0;
#pragma unroll
            for (int j = 0; j < 8; ++j) {
                uint64_t h01, h23;
                lds_v2u64_(ra_c + j * 16, h01, h23);
                fma2_(c0, wc2[2 * j],     h01);
                fma2_(c1, wc2[2 * j + 1], h23);
            }
            float x0, x1, y0, y1;
            unpack2_(c0, x0, x1);
            unpack2_(c1, y0, y1);
            redB[cc * 8 + sc] = (x0 + x1) + (y0 + y1);
        }
        __syncthreads();

        // ---- h update: 64 threads, one column each ----
        if (tid < 64) {
            float4 p0 = *(const float4*)&redB[tid * 8];
            float4 p1 = *(const float4*)&redB[tid * 8 + 4];
            float s = ((p0.x + p0.y) + (p0.z + p0.w))
                    + ((p1.x + p1.y) + (p1.z + p1.w))
                    + pbuf[cur + 128 + tid];
            float c  = tanhf(s);
            float u  = ubuf[tid];
            float hn = u * hbuf[rank * 64 + tid] + (1.f - u) * c;
            orow[(size_t)t * 256 + rank * 64 + tid] = hn;
            uint32_t a = hb + (rank * 64 + tid) * 4;
#pragma unroll
            for (int rk = 0; rk < 4; ++rk) st_cluster_f32_(a, rk, hn);
        }
        if (tid < 192) pbuf[nxt + tid] = pre_next;
        cluster_sync_();   // hbuf complete cluster-wide; pbuf ready
    }
}

// ---------------------------------------------------------------------------
extern "C" void kernel_launch(void* const* d_in, const int* in_sizes, int n_in,
                              void* d_out, int out_size) {
    const float* x  = (const float*)d_in[0];
    const float* h0 = (const float*)d_in[1];
    const float* Wg = (const float*)d_in[2];
    const float* bg = (const float*)d_in[3];
    const float* Wc = (const float*)d_in[4];
    const float* bc = (const float*)d_in[5];
    float* out = (float*)d_out;

    dim3 g1(12, 512);
    gemm_pre_kernel<<<g1, 256>>>(x, Wg, bg, Wc, bc);
    gru_rec_kernel<<<128, 512>>>(Wg, Wc, h0, out);
}